// round 11
// baseline (speedup 1.0000x reference)
#include <cuda_runtime.h>
#include <cuda_fp16.h>
#include <cstdint>

// Problem constants (fixed shapes)
#define T_TOK 4096
#define HDIM  1024
#define FDIM  4096
#define EDIM  8
#define BM 128
#define BN 128
#define BKH 64          // K halves per slab (4 x k16 mma steps)
#define ROWB 144        // smem row stride bytes (128 data + 16 pad)
#define PADROWS 9216    // 8192 + 8*128 worst-case segment padding
#define NS1 (HDIM / BKH)   // 16
#define NS2 (FDIM / BKH)   // 64
#define HSCALE 256.0f      // h scaling (exact power of 2)
#define HSCALE_INV 0.00390625f

// ---------------- scratch (static device globals; no allocation) ----------
__device__ __align__(16) __half g_wgup[(size_t)EDIM * 2 * FDIM * HDIM];
__device__ __align__(16) __half g_wdw[(size_t)EDIM * HDIM * FDIM];
__device__ __align__(16) __half g_x16[(size_t)T_TOK * HDIM];
__device__ __align__(16) __half g_h[(size_t)PADROWS * FDIM];
__device__ __align__(16) float  g_y[(size_t)PADROWS * HDIM];
__device__ int   g_perm_token[PADROWS];
__device__ float g_perm_weight[PADROWS];
__device__ int   g_token_pos[T_TOK * 2];
__device__ int   g_te[T_TOK * 2];
__device__ float g_tw[T_TOK * 2];
__device__ int   g_counts[EDIM];
__device__ int   g_cursor[EDIM];
__device__ int   g_off[EDIM + 1];

// ---------------- helpers ---------------------------------------------------
__device__ __forceinline__ uint32_t h2u(__half2 h) { return *(uint32_t*)&h; }

__device__ __forceinline__ uint32_t smem_u32(const void* p) {
    uint32_t a;
    asm("{ .reg .u64 t; cvta.to.shared.u64 t, %1; cvt.u32.u64 %0, t; }"
        : "=r"(a) : "l"(p));
    return a;
}

__device__ __forceinline__ void ldsm4(uint32_t& r0, uint32_t& r1,
                                      uint32_t& r2, uint32_t& r3, uint32_t addr) {
    asm volatile("ldmatrix.sync.aligned.m8n8.x4.shared.b16 {%0,%1,%2,%3}, [%4];"
                 : "=r"(r0), "=r"(r1), "=r"(r2), "=r"(r3) : "r"(addr));
}

__device__ __forceinline__ void mma_f16(float c[4], const uint32_t a[4],
                                        uint32_t b0, uint32_t b1) {
    asm volatile(
        "mma.sync.aligned.m16n8k16.row.col.f32.f16.f16.f32 "
        "{%0,%1,%2,%3}, {%4,%5,%6,%7}, {%8,%9}, {%0,%1,%2,%3};\n"
        : "+f"(c[0]), "+f"(c[1]), "+f"(c[2]), "+f"(c[3])
        : "r"(a[0]), "r"(a[1]), "r"(a[2]), "r"(a[3]), "r"(b0), "r"(b1));
}

// fp16-accumulate mma: D/C are 2 packed f16x2 regs {c0,c1},{c2,c3}
__device__ __forceinline__ void mma_f16a(uint32_t c[2], const uint32_t a[4],
                                         uint32_t b0, uint32_t b1) {
    asm volatile(
        "mma.sync.aligned.m16n8k16.row.col.f16.f16.f16.f16 "
        "{%0,%1}, {%2,%3,%4,%5}, {%6,%7}, {%0,%1};\n"
        : "+r"(c[0]), "+r"(c[1])
        : "r"(a[0]), "r"(a[1]), "r"(a[2]), "r"(a[3]), "r"(b0), "r"(b1));
}

// ---------------- fp32 -> fp16 conversion (one pass per tensor) ---------------
__global__ void cvt_kernel(const float* __restrict__ s, __half* __restrict__ d,
                           int n8) {
    int i = blockIdx.x * blockDim.x + threadIdx.x;
    if (i >= n8) return;
    const float4* s4 = (const float4*)s + (size_t)i * 2;
    float4 v0 = s4[0], v1 = s4[1];
    uint4 o;
    o.x = h2u(__floats2half2_rn(v0.x, v0.y));
    o.y = h2u(__floats2half2_rn(v0.z, v0.w));
    o.z = h2u(__floats2half2_rn(v1.x, v1.y));
    o.w = h2u(__floats2half2_rn(v1.z, v1.w));
    ((uint4*)d)[i] = o;
}

// ---------------- init ------------------------------------------------------
__global__ void init_kernel() {
    int i = blockIdx.x * blockDim.x + threadIdx.x;
    if (i < PADROWS) {
        g_perm_token[i] = -1;
        g_perm_weight[i] = 0.f;
    }
    if (i < EDIM) g_counts[i] = 0;
}

// ---------------- router: logits + softmax top2 -----------------------------
__global__ void __launch_bounds__(128) router_kernel(
    const float* __restrict__ x, const float* __restrict__ gw,
    float* __restrict__ logits_out) {
    __shared__ float sgw[EDIM * HDIM];
    int tid = threadIdx.x;
    for (int i = tid; i < EDIM * HDIM; i += 128) sgw[i] = gw[i];
    __syncthreads();

    int warp = tid >> 5, lane = tid & 31;
    int t = blockIdx.x * 4 + warp;
    const float* xr = x + (size_t)t * HDIM;

    float acc[EDIM];
#pragma unroll
    for (int e = 0; e < EDIM; e++) acc[e] = 0.f;
    for (int j = lane; j < HDIM; j += 32) {
        float xv = xr[j];
#pragma unroll
        for (int e = 0; e < EDIM; e++) acc[e] = fmaf(xv, sgw[e * HDIM + j], acc[e]);
    }
#pragma unroll
    for (int e = 0; e < EDIM; e++)
#pragma unroll
        for (int o = 16; o > 0; o >>= 1)
            acc[e] += __shfl_xor_sync(0xffffffffu, acc[e], o);

    if (lane == 0) {
#pragma unroll
        for (int e = 0; e < EDIM; e++) logits_out[t * EDIM + e] = acc[e];
        int e0 = 0; float l0 = acc[0];
#pragma unroll
        for (int e = 1; e < EDIM; e++) if (acc[e] > l0) { l0 = acc[e]; e0 = e; }
        int e1 = -1; float l1 = -3.4e38f;
#pragma unroll
        for (int e = 0; e < EDIM; e++)
            if (e != e0 && acc[e] > l1) { l1 = acc[e]; e1 = e; }
        float r = expf(l1 - l0);
        float w0 = 1.f / (1.f + r);
        float w1 = r / (1.f + r);
        g_te[t * 2 + 0] = e0; g_tw[t * 2 + 0] = w0;
        g_te[t * 2 + 1] = e1; g_tw[t * 2 + 1] = w1;
        atomicAdd(&g_counts[e0], 1);
        atomicAdd(&g_counts[e1], 1);
    }
}

// ---------------- scan ------------------------------------------------------
__global__ void scan_kernel() {
    int off = 0;
    for (int e = 0; e < EDIM; e++) {
        g_off[e] = off;
        g_cursor[e] = off;
        off += ((g_counts[e] + BM - 1) / BM) * BM;
    }
    g_off[EDIM] = off;
}

// ---------------- scatter ---------------------------------------------------
__global__ void scatter_kernel() {
    int t = blockIdx.x * blockDim.x + threadIdx.x;
    if (t >= T_TOK) return;
#pragma unroll
    for (int k = 0; k < 2; k++) {
        int e = g_te[t * 2 + k];
        int pos = atomicAdd(&g_cursor[e], 1);
        g_perm_token[pos] = t;
        g_perm_weight[pos] = g_tw[t * 2 + k];
        g_token_pos[t * 2 + k] = pos;
    }
}

// ---------------- GEMM1: h = silu(x@w1^T) * (x@w3^T) * route_w * 256 ---------
// unchanged fp32-acc structure (R8); epilogue scales h by HSCALE.
__global__ void __launch_bounds__(256, 1) gemm1_kernel() {
    extern __shared__ char sm1[];
    const uint32_t ABUF = 128 * ROWB;            // 18432
    const uint32_t GOFF = 128 * ROWB;            // up section inside B
    const uint32_t BBUF = 2 * 128 * ROWB;        // 36864
    char* Asm = sm1;
    char* Bsm = sm1 + 2 * ABUF;
    uint32_t asB = smem_u32(Asm);
    uint32_t bsB = smem_u32(Bsm);

    int m0 = blockIdx.x * BM;
    if (m0 >= g_off[EDIM]) return;
    int n0 = blockIdx.y * BN;
    int e = 0;
    while (m0 >= g_off[e + 1]) e++;

    int tid = threadIdx.x;
    int r = tid >> 1;
    int seg = tid & 1;

    int tok = g_perm_token[m0 + r];
    const __half* arow = (tok >= 0)
        ? g_x16 + (size_t)tok * HDIM + seg * 32 : nullptr;
    const __half* bgrow = g_wgup + ((size_t)e * 2 * FDIM + (n0 + r)) * HDIM + seg * 32;
    const __half* burow = bgrow + (size_t)FDIM * HDIM;
    uint32_t stoff = (uint32_t)(r * ROWB + seg * 64);

    int warp = tid >> 5, lane = tid & 31;
    int gid = lane >> 2, tig = lane & 3;
    int wm = (warp & 1) * 64;
    int wn = (warp >> 1) * 32;

    uint32_t aLrow = (uint32_t)(wm + (lane & 15));
    uint32_t aLcol = (uint32_t)((lane >> 4) * 16);
    uint32_t bLrow = (uint32_t)(wn + (lane & 7) + ((lane >> 4) & 1) * 8);
    uint32_t bLcol = (uint32_t)(((lane >> 3) & 1) * 16);

    float acc[2][4][4][4];
#pragma unroll
    for (int g = 0; g < 2; g++)
#pragma unroll
        for (int mt = 0; mt < 4; mt++)
#pragma unroll
            for (int nt = 0; nt < 4; nt++)
#pragma unroll
                for (int i = 0; i < 4; i++) acc[g][mt][nt][i] = 0.f;

    const uint4 z4 = make_uint4(0, 0, 0, 0);
    uint4 pA[4], pG[4], pU[4];
#pragma unroll
    for (int i = 0; i < 4; i++) {
        pA[i] = arow ? *(const uint4*)(arow + i * 8) : z4;
        pG[i] = *(const uint4*)(bgrow + i * 8);
        pU[i] = *(const uint4*)(burow + i * 8);
    }

    for (int s = 0; s < NS1; s++) {
        int buf = s & 1;
        char* At = Asm + buf * ABUF;
        char* Bt = Bsm + buf * BBUF;
#pragma unroll
        for (int i = 0; i < 4; i++) {
            *(uint4*)(At + stoff + i * 16) = pA[i];
            *(uint4*)(Bt + stoff + i * 16) = pG[i];
            *(uint4*)(Bt + GOFF + stoff + i * 16) = pU[i];
        }
        __syncthreads();

        if (s + 1 < NS1) {
            int k = (s + 1) * BKH;
#pragma unroll
            for (int i = 0; i < 4; i++) {
                pA[i] = arow ? *(const uint4*)(arow + k + i * 8) : z4;
                pG[i] = *(const uint4*)(bgrow + k + i * 8);
                pU[i] = *(const uint4*)(burow + k + i * 8);
            }
        }

        uint32_t aTile = asB + buf * ABUF;
        uint32_t bTile = bsB + buf * BBUF;
#pragma unroll
        for (int ks = 0; ks < 4; ks++) {
            uint32_t kbA = ks * 32 + aLcol;
            uint32_t kbB = ks * 32 + bLcol;
            uint32_t a[4][4];
#pragma unroll
            for (int mt = 0; mt < 4; mt++)
                ldsm4(a[mt][0], a[mt][1], a[mt][2], a[mt][3],
                      aTile + (aLrow + mt * 16) * ROWB + kbA);
#pragma unroll
            for (int g = 0; g < 2; g++) {
#pragma unroll
                for (int np = 0; np < 2; np++) {
                    uint32_t b0, b1, b2, b3;
                    ldsm4(b0, b1, b2, b3,
                          bTile + g * GOFF + (bLrow + np * 16) * ROWB + kbB);
#pragma unroll
                    for (int mt = 0; mt < 4; mt++) {
                        mma_f16(acc[g][mt][np * 2 + 0], a[mt], b0, b1);
                        mma_f16(acc[g][mt][np * 2 + 1], a[mt], b2, b3);
                    }
                }
            }
        }
    }

    // epilogue: silu(gate) * up * routing_weight * HSCALE -> fp16 g_h
#pragma unroll
    for (int mt = 0; mt < 4; mt++) {
        int rbase = m0 + wm + mt * 16 + gid;
        float wA = g_perm_weight[rbase] * HSCALE;
        float wB = g_perm_weight[rbase + 8] * HSCALE;
#pragma unroll
        for (int nt = 0; nt < 4; nt++) {
            int cbase = n0 + wn + nt * 8 + 2 * tig;
            float h0 = (acc[0][mt][nt][0] / (1.f + expf(-acc[0][mt][nt][0]))) *
                       acc[1][mt][nt][0] * wA;
            float h1 = (acc[0][mt][nt][1] / (1.f + expf(-acc[0][mt][nt][1]))) *
                       acc[1][mt][nt][1] * wA;
            float h2 = (acc[0][mt][nt][2] / (1.f + expf(-acc[0][mt][nt][2]))) *
                       acc[1][mt][nt][2] * wB;
            float h3 = (acc[0][mt][nt][3] / (1.f + expf(-acc[0][mt][nt][3]))) *
                       acc[1][mt][nt][3] * wB;
            *(uint32_t*)&g_h[(size_t)rbase * FDIM + cbase] =
                h2u(__floats2half2_rn(h0, h1));
            *(uint32_t*)&g_h[(size_t)(rbase + 8) * FDIM + cbase] =
                h2u(__floats2half2_rn(h2, h3));
        }
    }
}

// ---------------- GEMM2: y = (h_scaled @ w2^T) ; fp16-acc chains (K=32) -------
__global__ void __launch_bounds__(256, 1) gemm2_kernel() {
    extern __shared__ char sm2[];
    const uint32_t ABUF = 128 * ROWB;
    const uint32_t BBUF = 128 * ROWB;
    char* Asm = sm2;
    char* Bsm = sm2 + 2 * ABUF;
    uint32_t asB = smem_u32(Asm);
    uint32_t bsB = smem_u32(Bsm);

    int m0 = blockIdx.x * BM;
    if (m0 >= g_off[EDIM]) return;
    int n0 = blockIdx.y * BN;
    int e = 0;
    while (m0 >= g_off[e + 1]) e++;

    int tid = threadIdx.x;
    int r = tid >> 1;
    int seg = tid & 1;

    const __half* arow = g_h + (size_t)(m0 + r) * FDIM + seg * 32;
    const __half* brow = g_wdw + ((size_t)e * HDIM + (n0 + r)) * FDIM + seg * 32;
    uint32_t stoff = (uint32_t)(r * ROWB + seg * 64);

    int warp = tid >> 5, lane = tid & 31;
    int gid = lane >> 2, tig = lane & 3;
    int wm = (warp & 1) * 64;
    int wn = (warp >> 1) * 32;

    uint32_t aLrow = (uint32_t)(wm + (lane & 15));
    uint32_t aLcol = (uint32_t)((lane >> 4) * 16);
    uint32_t bLrow = (uint32_t)(wn + (lane & 7) + ((lane >> 4) & 1) * 8);
    uint32_t bLcol = (uint32_t)(((lane >> 3) & 1) * 16);

    float acc[4][4][4];
#pragma unroll
    for (int mt = 0; mt < 4; mt++)
#pragma unroll
        for (int nt = 0; nt < 4; nt++)
#pragma unroll
            for (int i = 0; i < 4; i++) acc[mt][nt][i] = 0.f;

    uint4 pA[4], pB[4];
#pragma unroll
    for (int i = 0; i < 4; i++) {
        pA[i] = *(const uint4*)(arow + i * 8);
        pB[i] = *(const uint4*)(brow + i * 8);
    }

    for (int s = 0; s < NS2; s++) {
        int buf = s & 1;
        char* At = Asm + buf * ABUF;
        char* Bt = Bsm + buf * BBUF;
#pragma unroll
        for (int i = 0; i < 4; i++) {
            *(uint4*)(At + stoff + i * 16) = pA[i];
            *(uint4*)(Bt + stoff + i * 16) = pB[i];
        }
        __syncthreads();

        if (s + 1 < NS2) {
            int k = (s + 1) * BKH;
#pragma unroll
            for (int i = 0; i < 4; i++) {
                pA[i] = *(const uint4*)(arow + k + i * 8);
                pB[i] = *(const uint4*)(brow + k + i * 8);
            }
        }

        uint32_t aTile = asB + buf * ABUF;
        uint32_t bTile = bsB + buf * BBUF;

        uint32_t c16[16][2];     // fp16 chain accs: [mt*4 + np*2 + j]
#pragma unroll
        for (int t = 0; t < 16; t++) { c16[t][0] = 0; c16[t][1] = 0; }

#pragma unroll
        for (int ks = 0; ks < 4; ks++) {
            uint32_t kbA = ks * 32 + aLcol;
            uint32_t kbB = ks * 32 + bLcol;
            uint32_t a[4][4];
#pragma unroll
            for (int mt = 0; mt < 4; mt++)
                ldsm4(a[mt][0], a[mt][1], a[mt][2], a[mt][3],
                      aTile + (aLrow + mt * 16) * ROWB + kbA);
#pragma unroll
            for (int np = 0; np < 2; np++) {
                uint32_t b0, b1, b2, b3;
                ldsm4(b0, b1, b2, b3,
                      bTile + (bLrow + np * 16) * ROWB + kbB);
#pragma unroll
                for (int mt = 0; mt < 4; mt++) {
                    mma_f16a(c16[mt * 4 + np * 2 + 0], a[mt], b0, b1);
                    mma_f16a(c16[mt * 4 + np * 2 + 1], a[mt], b2, b3);
                }
            }
            if (ks == 1 || ks == 3) {   // spill fp16 chains -> fp32 masters
#pragma unroll
                for (int mt = 0; mt < 4; mt++)
#pragma unroll
                    for (int nt = 0; nt < 4; nt++) {
                        uint32_t* c = c16[mt * 4 + nt];
                        float2 lo = __half22float2(*(__half2*)&c[0]);
                        float2 hi = __half22float2(*(__half2*)&c[1]);
                        acc[mt][nt][0] += lo.x;
                        acc[mt][nt][1] += lo.y;
                        acc[mt][nt][2] += hi.x;
                        acc[mt][nt][3] += hi.y;
                        c[0] = 0; c[1] = 0;
                    }
            }
        }
    }

#pragma unroll
    for (int mt = 0; mt < 4; mt++) {
        int rbase = m0 + wm + mt * 16 + gid;
#pragma unroll
        for (int nt = 0; nt < 4; nt++) {
            int cbase = n0 + wn + nt * 8 + 2 * tig;
            *(float2*)&g_y[(size_t)rbase * HDIM + cbase] =
                make_float2(acc[mt][nt][0], acc[mt][nt][1]);
            *(float2*)&g_y[(size_t)(rbase + 8) * HDIM + cbase] =
                make_float2(acc[mt][nt][2], acc[mt][nt][3]);
        }
    }
}

// ---------------- combine: out[t] = (y[pos0] + y[pos1]) / HSCALE --------------
__global__ void combine_kernel(float* __restrict__ out) {
    int i = blockIdx.x * blockDim.x + threadIdx.x;
    if (i >= T_TOK * HDIM / 4) return;
    int t = i >> 8, n4 = i & 255;
    int p0 = g_token_pos[t * 2 + 0];
    int p1 = g_token_pos[t * 2 + 1];
    float4 a = *(const float4*)&g_y[(size_t)p0 * HDIM + n4 * 4];
    float4 b = *(const float4*)&g_y[(size_t)p1 * HDIM + n4 * 4];
    float4 o = make_float4((a.x + b.x) * HSCALE_INV, (a.y + b.y) * HSCALE_INV,
                           (a.z + b.z) * HSCALE_INV, (a.w + b.w) * HSCALE_INV);
    *(float4*)&out[(size_t)t * HDIM + n4 * 4] = o;
}

// ---------------- launcher ----------------------------------------------------
extern "C" void kernel_launch(void* const* d_in, const int* in_sizes, int n_in,
                              void* d_out, int out_size) {
    const float* x   = (const float*)d_in[0];   // (2,2048,1024)
    const float* gw  = (const float*)d_in[1];   // (8,1024)
    const float* gup = (const float*)d_in[2];   // (8,8192,1024)
    const float* dw  = (const float*)d_in[3];   // (8,1024,4096)
    float* out = (float*)d_out;                 // out (4194304) ++ logits (32768)
    float* logits = out + (size_t)T_TOK * HDIM;

    const int smem1 = 2 * 128 * ROWB + 2 * 2 * 128 * ROWB;  // 110592 B
    const int smem2 = 2 * 128 * ROWB + 2 * 128 * ROWB;      //  73728 B
    cudaFuncSetAttribute(gemm1_kernel, cudaFuncAttributeMaxDynamicSharedMemorySize, smem1);
    cudaFuncSetAttribute(gemm2_kernel, cudaFuncAttributeMaxDynamicSharedMemorySize, smem2);

    __half* d_wgup; cudaGetSymbolAddress((void**)&d_wgup, g_wgup);
    __half* d_wdw;  cudaGetSymbolAddress((void**)&d_wdw,  g_wdw);
    __half* d_x16;  cudaGetSymbolAddress((void**)&d_x16,  g_x16);

    static cudaStream_t s2 = nullptr, s3 = nullptr;
    static cudaEvent_t evFork = nullptr, evDW = nullptr, evRoute = nullptr;
    if (!s2) {
        cudaStreamCreateWithFlags(&s2, cudaStreamNonBlocking);
        cudaStreamCreateWithFlags(&s3, cudaStreamNonBlocking);
        cudaEventCreateWithFlags(&evFork, cudaEventDisableTiming);
        cudaEventCreateWithFlags(&evDW, cudaEventDisableTiming);
        cudaEventCreateWithFlags(&evRoute, cudaEventDisableTiming);
    }

    cudaEventRecord(evFork, 0);
    cudaStreamWaitEvent(s2, evFork, 0);
    cudaStreamWaitEvent(s3, evFork, 0);

    cvt_kernel<<<(EDIM * HDIM * FDIM / 8 + 255) / 256, 256, 0, s2>>>(
        dw, d_wdw, EDIM * HDIM * FDIM / 8);
    cudaEventRecord(evDW, s2);

    init_kernel<<<(PADROWS + 255) / 256, 256, 0, s3>>>();
    router_kernel<<<T_TOK / 4, 128, 0, s3>>>(x, gw, logits);
    scan_kernel<<<1, 1, 0, s3>>>();
    scatter_kernel<<<(T_TOK + 255) / 256, 256, 0, s3>>>();
    cudaEventRecord(evRoute, s3);

    cvt_kernel<<<(T_TOK * HDIM / 8 + 255) / 256, 256>>>(x, d_x16,
        T_TOK * HDIM / 8);
    cvt_kernel<<<(EDIM * 2 * FDIM * HDIM / 8 + 255) / 256, 256>>>(gup, d_wgup,
        EDIM * 2 * FDIM * HDIM / 8);

    cudaStreamWaitEvent(0, evRoute, 0);
    gemm1_kernel<<<dim3(PADROWS / BM, FDIM / BN), 256, smem1>>>();

    cudaStreamWaitEvent(0, evDW, 0);
    gemm2_kernel<<<dim3(PADROWS / BM, HDIM / BN), 256, smem2>>>();
    combine_kernel<<<(T_TOK * HDIM / 4 + 255) / 256, 256>>>(out);
    (void)in_sizes; (void)n_in; (void)out_size;
}

// round 12
// speedup vs baseline: 1.1174x; 1.1174x over previous
#include <cuda_runtime.h>
#include <cuda_fp16.h>
#include <cstdint>

// Problem constants (fixed shapes)
#define T_TOK 4096
#define HDIM  1024
#define FDIM  4096
#define EDIM  8
#define BM 128
#define BN 128
#define BKH 64          // K halves per slab (4 x k16 mma steps)
#define ROWB 144        // smem row stride bytes (128 data + 16 pad)
#define PADROWS 9216    // 8192 + 8*128 worst-case segment padding
#define NS1 (HDIM / BKH)   // 16
#define NS2 (FDIM / BKH)   // 64

// ---------------- scratch (static device globals; no allocation) ----------
__device__ __align__(16) __half g_wgup[(size_t)EDIM * 2 * FDIM * HDIM];
__device__ __align__(16) __half g_wdw[(size_t)EDIM * HDIM * FDIM];
__device__ __align__(16) __half g_x16[(size_t)T_TOK * HDIM];
__device__ __align__(16) __half g_h[(size_t)PADROWS * FDIM];
__device__ int   g_perm_token[PADROWS];
__device__ float g_perm_weight[PADROWS];
__device__ int   g_te[T_TOK * 2];
__device__ float g_tw[T_TOK * 2];
__device__ int   g_counts[EDIM];
__device__ int   g_cursor[EDIM];
__device__ int   g_off[EDIM + 1];

// ---------------- helpers ---------------------------------------------------
__device__ __forceinline__ uint32_t h2u(__half2 h) { return *(uint32_t*)&h; }

__device__ __forceinline__ uint32_t smem_u32(const void* p) {
    uint32_t a;
    asm("{ .reg .u64 t; cvta.to.shared.u64 t, %1; cvt.u32.u64 %0, t; }"
        : "=r"(a) : "l"(p));
    return a;
}

__device__ __forceinline__ void ldsm4(uint32_t& r0, uint32_t& r1,
                                      uint32_t& r2, uint32_t& r3, uint32_t addr) {
    asm volatile("ldmatrix.sync.aligned.m8n8.x4.shared.b16 {%0,%1,%2,%3}, [%4];"
                 : "=r"(r0), "=r"(r1), "=r"(r2), "=r"(r3) : "r"(addr));
}

__device__ __forceinline__ void mma_f16(float c[4], const uint32_t a[4],
                                        uint32_t b0, uint32_t b1) {
    asm volatile(
        "mma.sync.aligned.m16n8k16.row.col.f32.f16.f16.f32 "
        "{%0,%1,%2,%3}, {%4,%5,%6,%7}, {%8,%9}, {%0,%1,%2,%3};\n"
        : "+f"(c[0]), "+f"(c[1]), "+f"(c[2]), "+f"(c[3])
        : "r"(a[0]), "r"(a[1]), "r"(a[2]), "r"(a[3]), "r"(b0), "r"(b1));
}

// ---------------- fp32 -> fp16 conversion (flat) -------------------------------
__global__ void cvt_kernel(const float* __restrict__ s, __half* __restrict__ d,
                           int n8) {
    int i = blockIdx.x * blockDim.x + threadIdx.x;
    if (i >= n8) return;
    const float4* s4 = (const float4*)s + (size_t)i * 2;
    float4 v0 = s4[0], v1 = s4[1];
    uint4 o;
    o.x = h2u(__floats2half2_rn(v0.x, v0.y));
    o.y = h2u(__floats2half2_rn(v0.z, v0.w));
    o.z = h2u(__floats2half2_rn(v1.x, v1.y));
    o.w = h2u(__floats2half2_rn(v1.z, v1.w));
    ((uint4*)d)[i] = o;
}

// ---------------- cvt for one column-half of gate_up ---------------------------
// half h covers h-columns n0 in [h*2048, (h+1)*2048): gate rows e*8192+h*2048+r
// and up rows e*8192+4096+h*2048+r, r in [0,2048).
__global__ void cvt_gup_half_kernel(const float* __restrict__ s,
                                    __half* __restrict__ d, int half) {
    int i = blockIdx.x * blockDim.x + threadIdx.x;   // over E*4096*128 chunks
    if (i >= EDIM * 4096 * 128) return;
    int rowIdx = i >> 7;
    int chunk = i & 127;
    int e = rowIdx >> 12;
    int rr = rowIdx & 4095;
    int isUp = rr >> 11;
    int r = rr & 2047;
    size_t srcRow = (size_t)e * 8192 + (size_t)isUp * 4096 +
                    (size_t)half * 2048 + (size_t)r;
    size_t off8 = srcRow * 128 + chunk;              // in 8-element units
    const float4* s4 = (const float4*)s + off8 * 2;
    float4 v0 = s4[0], v1 = s4[1];
    uint4 o;
    o.x = h2u(__floats2half2_rn(v0.x, v0.y));
    o.y = h2u(__floats2half2_rn(v0.z, v0.w));
    o.z = h2u(__floats2half2_rn(v1.x, v1.y));
    o.w = h2u(__floats2half2_rn(v1.z, v1.w));
    ((uint4*)d)[off8] = o;
}

// ---------------- init + zero output ------------------------------------------
__global__ void init_kernel() {
    int i = blockIdx.x * blockDim.x + threadIdx.x;
    if (i < PADROWS) {
        g_perm_token[i] = -1;
        g_perm_weight[i] = 0.f;
    }
    if (i < EDIM) g_counts[i] = 0;
}

__global__ void zero_out_kernel(float* __restrict__ out) {
    int i = blockIdx.x * blockDim.x + threadIdx.x;
    if (i < T_TOK * HDIM / 4)
        ((float4*)out)[i] = make_float4(0.f, 0.f, 0.f, 0.f);
}

// ---------------- router: logits + softmax top2 -----------------------------
__global__ void __launch_bounds__(128) router_kernel(
    const float* __restrict__ x, const float* __restrict__ gw,
    float* __restrict__ logits_out) {
    __shared__ float sgw[EDIM * HDIM];
    int tid = threadIdx.x;
    for (int i = tid; i < EDIM * HDIM; i += 128) sgw[i] = gw[i];
    __syncthreads();

    int warp = tid >> 5, lane = tid & 31;
    int t = blockIdx.x * 4 + warp;
    const float* xr = x + (size_t)t * HDIM;

    float acc[EDIM];
#pragma unroll
    for (int e = 0; e < EDIM; e++) acc[e] = 0.f;
    for (int j = lane; j < HDIM; j += 32) {
        float xv = xr[j];
#pragma unroll
        for (int e = 0; e < EDIM; e++) acc[e] = fmaf(xv, sgw[e * HDIM + j], acc[e]);
    }
#pragma unroll
    for (int e = 0; e < EDIM; e++)
#pragma unroll
        for (int o = 16; o > 0; o >>= 1)
            acc[e] += __shfl_xor_sync(0xffffffffu, acc[e], o);

    if (lane == 0) {
#pragma unroll
        for (int e = 0; e < EDIM; e++) logits_out[t * EDIM + e] = acc[e];
        int e0 = 0; float l0 = acc[0];
#pragma unroll
        for (int e = 1; e < EDIM; e++) if (acc[e] > l0) { l0 = acc[e]; e0 = e; }
        int e1 = -1; float l1 = -3.4e38f;
#pragma unroll
        for (int e = 0; e < EDIM; e++)
            if (e != e0 && acc[e] > l1) { l1 = acc[e]; e1 = e; }
        float r = expf(l1 - l0);
        float w0 = 1.f / (1.f + r);
        float w1 = r / (1.f + r);
        g_te[t * 2 + 0] = e0; g_tw[t * 2 + 0] = w0;
        g_te[t * 2 + 1] = e1; g_tw[t * 2 + 1] = w1;
        atomicAdd(&g_counts[e0], 1);
        atomicAdd(&g_counts[e1], 1);
    }
}

// ---------------- scan ------------------------------------------------------
__global__ void scan_kernel() {
    int off = 0;
    for (int e = 0; e < EDIM; e++) {
        g_off[e] = off;
        g_cursor[e] = off;
        off += ((g_counts[e] + BM - 1) / BM) * BM;
    }
    g_off[EDIM] = off;
}

// ---------------- scatter ---------------------------------------------------
__global__ void scatter_kernel() {
    int t = blockIdx.x * blockDim.x + threadIdx.x;
    if (t >= T_TOK) return;
#pragma unroll
    for (int k = 0; k < 2; k++) {
        int e = g_te[t * 2 + k];
        int pos = atomicAdd(&g_cursor[e], 1);
        g_perm_token[pos] = t;
        g_perm_weight[pos] = g_tw[t * 2 + k];
    }
}

// ---------------- GEMM1: h = silu(x@w1^T) * (x@w3^T) * route_w ---------------
// 256 threads / 8 warps; fp16; ldmatrix; reg prefetch; ONE barrier per slab.
__global__ void __launch_bounds__(256, 1) gemm1_kernel(int n0base) {
    extern __shared__ char sm1[];
    const uint32_t ABUF = 128 * ROWB;            // 18432
    const uint32_t GOFF = 128 * ROWB;            // up section inside B
    const uint32_t BBUF = 2 * 128 * ROWB;        // 36864
    char* Asm = sm1;
    char* Bsm = sm1 + 2 * ABUF;
    uint32_t asB = smem_u32(Asm);
    uint32_t bsB = smem_u32(Bsm);

    int m0 = blockIdx.x * BM;
    if (m0 >= g_off[EDIM]) return;
    int n0 = n0base + blockIdx.y * BN;
    int e = 0;
    while (m0 >= g_off[e + 1]) e++;

    int tid = threadIdx.x;
    int r = tid >> 1;             // staging row 0..127
    int seg = tid & 1;            // 64-byte half-row segment

    int tok = g_perm_token[m0 + r];
    const __half* arow = (tok >= 0)
        ? g_x16 + (size_t)tok * HDIM + seg * 32 : nullptr;
    const __half* bgrow = g_wgup + ((size_t)e * 2 * FDIM + (n0 + r)) * HDIM + seg * 32;
    const __half* burow = bgrow + (size_t)FDIM * HDIM;
    uint32_t stoff = (uint32_t)(r * ROWB + seg * 64);

    int warp = tid >> 5, lane = tid & 31;
    int gid = lane >> 2, tig = lane & 3;
    int wm = (warp & 1) * 64;
    int wn = (warp >> 1) * 32;

    uint32_t aLrow = (uint32_t)(wm + (lane & 15));
    uint32_t aLcol = (uint32_t)((lane >> 4) * 16);
    uint32_t bLrow = (uint32_t)(wn + (lane & 7) + ((lane >> 4) & 1) * 8);
    uint32_t bLcol = (uint32_t)(((lane >> 3) & 1) * 16);

    float acc[2][4][4][4];
#pragma unroll
    for (int g = 0; g < 2; g++)
#pragma unroll
        for (int mt = 0; mt < 4; mt++)
#pragma unroll
            for (int nt = 0; nt < 4; nt++)
#pragma unroll
                for (int i = 0; i < 4; i++) acc[g][mt][nt][i] = 0.f;

    const uint4 z4 = make_uint4(0, 0, 0, 0);
    uint4 pA[4], pG[4], pU[4];
#pragma unroll
    for (int i = 0; i < 4; i++) {
        pA[i] = arow ? *(const uint4*)(arow + i * 8) : z4;
        pG[i] = *(const uint4*)(bgrow + i * 8);
        pU[i] = *(const uint4*)(burow + i * 8);
    }

    for (int s = 0; s < NS1; s++) {
        int buf = s & 1;
        char* At = Asm + buf * ABUF;
        char* Bt = Bsm + buf * BBUF;
#pragma unroll
        for (int i = 0; i < 4; i++) {
            *(uint4*)(At + stoff + i * 16) = pA[i];
            *(uint4*)(Bt + stoff + i * 16) = pG[i];
            *(uint4*)(Bt + GOFF + stoff + i * 16) = pU[i];
        }
        __syncthreads();     // single barrier per slab (double-buffer safe)

        if (s + 1 < NS1) {
            int k = (s + 1) * BKH;
#pragma unroll
            for (int i = 0; i < 4; i++) {
                pA[i] = arow ? *(const uint4*)(arow + k + i * 8) : z4;
                pG[i] = *(const uint4*)(bgrow + k + i * 8);
                pU[i] = *(const uint4*)(burow + k + i * 8);
            }
        }

        uint32_t aTile = asB + buf * ABUF;
        uint32_t bTile = bsB + buf * BBUF;
#pragma unroll
        for (int ks = 0; ks < 4; ks++) {
            uint32_t kbA = ks * 32 + aLcol;
            uint32_t kbB = ks * 32 + bLcol;
            uint32_t a[4][4];
#pragma unroll
            for (int mt = 0; mt < 4; mt++)
                ldsm4(a[mt][0], a[mt][1], a[mt][2], a[mt][3],
                      aTile + (aLrow + mt * 16) * ROWB + kbA);
#pragma unroll
            for (int g = 0; g < 2; g++) {
#pragma unroll
                for (int np = 0; np < 2; np++) {
                    uint32_t b0, b1, b2, b3;
                    ldsm4(b0, b1, b2, b3,
                          bTile + g * GOFF + (bLrow + np * 16) * ROWB + kbB);
#pragma unroll
                    for (int mt = 0; mt < 4; mt++) {
                        mma_f16(acc[g][mt][np * 2 + 0], a[mt], b0, b1);
                        mma_f16(acc[g][mt][np * 2 + 1], a[mt], b2, b3);
                    }
                }
            }
        }
    }

    // epilogue: silu(gate) * up * routing_weight -> fp16 g_h
#pragma unroll
    for (int mt = 0; mt < 4; mt++) {
        int rbase = m0 + wm + mt * 16 + gid;
        float wA = g_perm_weight[rbase];
        float wB = g_perm_weight[rbase + 8];
#pragma unroll
        for (int nt = 0; nt < 4; nt++) {
            int cbase = n0 + wn + nt * 8 + 2 * tig;
            float h0 = (acc[0][mt][nt][0] / (1.f + expf(-acc[0][mt][nt][0]))) *
                       acc[1][mt][nt][0] * wA;
            float h1 = (acc[0][mt][nt][1] / (1.f + expf(-acc[0][mt][nt][1]))) *
                       acc[1][mt][nt][1] * wA;
            float h2 = (acc[0][mt][nt][2] / (1.f + expf(-acc[0][mt][nt][2]))) *
                       acc[1][mt][nt][2] * wB;
            float h3 = (acc[0][mt][nt][3] / (1.f + expf(-acc[0][mt][nt][3]))) *
                       acc[1][mt][nt][3] * wB;
            *(uint32_t*)&g_h[(size_t)rbase * FDIM + cbase] =
                h2u(__floats2half2_rn(h0, h1));
            *(uint32_t*)&g_h[(size_t)(rbase + 8) * FDIM + cbase] =
                h2u(__floats2half2_rn(h2, h3));
        }
    }
}

// ---------------- GEMM2: out[tok] += h @ w2^T (combine fused via atomics) -----
__global__ void __launch_bounds__(256, 1) gemm2_kernel(float* __restrict__ out) {
    extern __shared__ char sm2[];
    const uint32_t ABUF = 128 * ROWB;
    const uint32_t BBUF = 128 * ROWB;
    char* Asm = sm2;
    char* Bsm = sm2 + 2 * ABUF;
    uint32_t asB = smem_u32(Asm);
    uint32_t bsB = smem_u32(Bsm);

    int m0 = blockIdx.x * BM;
    if (m0 >= g_off[EDIM]) return;
    int n0 = blockIdx.y * BN;   // over HDIM
    int e = 0;
    while (m0 >= g_off[e + 1]) e++;

    int tid = threadIdx.x;
    int r = tid >> 1;
    int seg = tid & 1;

    const __half* arow = g_h + (size_t)(m0 + r) * FDIM + seg * 32;
    const __half* brow = g_wdw + ((size_t)e * HDIM + (n0 + r)) * FDIM + seg * 32;
    uint32_t stoff = (uint32_t)(r * ROWB + seg * 64);

    int warp = tid >> 5, lane = tid & 31;
    int gid = lane >> 2, tig = lane & 3;
    int wm = (warp & 1) * 64;
    int wn = (warp >> 1) * 32;

    uint32_t aLrow = (uint32_t)(wm + (lane & 15));
    uint32_t aLcol = (uint32_t)((lane >> 4) * 16);
    uint32_t bLrow = (uint32_t)(wn + (lane & 7) + ((lane >> 4) & 1) * 8);
    uint32_t bLcol = (uint32_t)(((lane >> 3) & 1) * 16);

    float acc[4][4][4];
#pragma unroll
    for (int mt = 0; mt < 4; mt++)
#pragma unroll
        for (int nt = 0; nt < 4; nt++)
#pragma unroll
            for (int i = 0; i < 4; i++) acc[mt][nt][i] = 0.f;

    uint4 pA[4], pB[4];
#pragma unroll
    for (int i = 0; i < 4; i++) {
        pA[i] = *(const uint4*)(arow + i * 8);
        pB[i] = *(const uint4*)(brow + i * 8);
    }

    for (int s = 0; s < NS2; s++) {
        int buf = s & 1;
        char* At = Asm + buf * ABUF;
        char* Bt = Bsm + buf * BBUF;
#pragma unroll
        for (int i = 0; i < 4; i++) {
            *(uint4*)(At + stoff + i * 16) = pA[i];
            *(uint4*)(Bt + stoff + i * 16) = pB[i];
        }
        __syncthreads();     // single barrier per slab

        if (s + 1 < NS2) {
            int k = (s + 1) * BKH;
#pragma unroll
            for (int i = 0; i < 4; i++) {
                pA[i] = *(const uint4*)(arow + k + i * 8);
                pB[i] = *(const uint4*)(brow + k + i * 8);
            }
        }

        uint32_t aTile = asB + buf * ABUF;
        uint32_t bTile = bsB + buf * BBUF;
#pragma unroll
        for (int ks = 0; ks < 4; ks++) {
            uint32_t kbA = ks * 32 + aLcol;
            uint32_t kbB = ks * 32 + bLcol;
            uint32_t a[4][4];
#pragma unroll
            for (int mt = 0; mt < 4; mt++)
                ldsm4(a[mt][0], a[mt][1], a[mt][2], a[mt][3],
                      aTile + (aLrow + mt * 16) * ROWB + kbA);
#pragma unroll
            for (int np = 0; np < 2; np++) {
                uint32_t b0, b1, b2, b3;
                ldsm4(b0, b1, b2, b3,
                      bTile + (bLrow + np * 16) * ROWB + kbB);
#pragma unroll
                for (int mt = 0; mt < 4; mt++) {
                    mma_f16(acc[mt][np * 2 + 0], a[mt], b0, b1);
                    mma_f16(acc[mt][np * 2 + 1], a[mt], b2, b3);
                }
            }
        }
    }

    // epilogue: atomically accumulate into out[token] (exactly 2 contributors
    // per element across the whole grid -> commutative add -> deterministic).
#pragma unroll
    for (int mt = 0; mt < 4; mt++) {
        int rbase = m0 + wm + mt * 16 + gid;
        int tok0 = g_perm_token[rbase];
        int tok1 = g_perm_token[rbase + 8];
#pragma unroll
        for (int nt = 0; nt < 4; nt++) {
            int cbase = n0 + wn + nt * 8 + 2 * tig;
            if (tok0 >= 0) {
                atomicAdd(&out[(size_t)tok0 * HDIM + cbase], acc[mt][nt][0]);
                atomicAdd(&out[(size_t)tok0 * HDIM + cbase + 1], acc[mt][nt][1]);
            }
            if (tok1 >= 0) {
                atomicAdd(&out[(size_t)tok1 * HDIM + cbase], acc[mt][nt][2]);
                atomicAdd(&out[(size_t)tok1 * HDIM + cbase + 1], acc[mt][nt][3]);
            }
        }
    }
}

// ---------------- launcher ----------------------------------------------------
extern "C" void kernel_launch(void* const* d_in, const int* in_sizes, int n_in,
                              void* d_out, int out_size) {
    const float* x   = (const float*)d_in[0];   // (2,2048,1024)
    const float* gw  = (const float*)d_in[1];   // (8,1024)
    const float* gup = (const float*)d_in[2];   // (8,8192,1024)
    const float* dw  = (const float*)d_in[3];   // (8,1024,4096)
    float* out = (float*)d_out;                 // out (4194304) ++ logits (32768)
    float* logits = out + (size_t)T_TOK * HDIM;

    const int smem1 = 2 * 128 * ROWB + 2 * 2 * 128 * ROWB;  // 110592 B
    const int smem2 = 2 * 128 * ROWB + 2 * 128 * ROWB;      //  73728 B
    cudaFuncSetAttribute(gemm1_kernel, cudaFuncAttributeMaxDynamicSharedMemorySize, smem1);
    cudaFuncSetAttribute(gemm2_kernel, cudaFuncAttributeMaxDynamicSharedMemorySize, smem2);

    __half* d_wgup; cudaGetSymbolAddress((void**)&d_wgup, g_wgup);
    __half* d_wdw;  cudaGetSymbolAddress((void**)&d_wdw,  g_wdw);
    __half* d_x16;  cudaGetSymbolAddress((void**)&d_x16,  g_x16);

    static cudaStream_t s2 = nullptr, s3 = nullptr;
    static cudaEvent_t evFork = nullptr, evCvt0 = nullptr, evH1 = nullptr,
                       evDW = nullptr, evRoute = nullptr;
    if (!s2) {
        cudaStreamCreateWithFlags(&s2, cudaStreamNonBlocking);
        cudaStreamCreateWithFlags(&s3, cudaStreamNonBlocking);
        cudaEventCreateWithFlags(&evFork, cudaEventDisableTiming);
        cudaEventCreateWithFlags(&evCvt0, cudaEventDisableTiming);
        cudaEventCreateWithFlags(&evH1, cudaEventDisableTiming);
        cudaEventCreateWithFlags(&evDW, cudaEventDisableTiming);
        cudaEventCreateWithFlags(&evRoute, cudaEventDisableTiming);
    }

    cudaEventRecord(evFork, 0);
    cudaStreamWaitEvent(s3, evFork, 0);

    // s3: output zero + routing chain (hidden under cvts)
    zero_out_kernel<<<(T_TOK * HDIM / 4 + 255) / 256, 256, 0, s3>>>(out);
    init_kernel<<<(PADROWS + 255) / 256, 256, 0, s3>>>();
    router_kernel<<<T_TOK / 4, 128, 0, s3>>>(x, gw, logits);
    scan_kernel<<<1, 1, 0, s3>>>();
    scatter_kernel<<<(T_TOK + 255) / 256, 256, 0, s3>>>();
    cudaEventRecord(evRoute, s3);

    // main: x cvt + first gate_up half (serial prefix kept minimal)
    cvt_kernel<<<(T_TOK * HDIM / 8 + 255) / 256, 256>>>(x, d_x16,
        T_TOK * HDIM / 8);
    cvt_gup_half_kernel<<<(EDIM * 4096 * 128 + 255) / 256, 256>>>(gup, d_wgup, 0);
    cudaEventRecord(evCvt0, 0);

    // s2: second gate_up half + down weights, overlapping gemm1 half 0
    cudaStreamWaitEvent(s2, evCvt0, 0);
    cvt_gup_half_kernel<<<(EDIM * 4096 * 128 + 255) / 256, 256, 0, s2>>>(
        gup, d_wgup, 1);
    cudaEventRecord(evH1, s2);
    cvt_kernel<<<(EDIM * HDIM * FDIM / 8 + 255) / 256, 256, 0, s2>>>(
        dw, d_wdw, EDIM * HDIM * FDIM / 8);
    cudaEventRecord(evDW, s2);

    // main: GEMM pipeline
    cudaStreamWaitEvent(0, evRoute, 0);
    gemm1_kernel<<<dim3(PADROWS / BM, 16), 256, smem1>>>(0);
    cudaStreamWaitEvent(0, evH1, 0);
    gemm1_kernel<<<dim3(PADROWS / BM, 16), 256, smem1>>>(2048);
    cudaStreamWaitEvent(0, evDW, 0);
    gemm2_kernel<<<dim3(PADROWS / BM, HDIM / BN), 256, smem2>>>(out);
    (void)in_sizes; (void)n_in; (void)out_size;
}

// round 13
// speedup vs baseline: 1.1333x; 1.0142x over previous
#include <cuda_runtime.h>
#include <cuda_fp16.h>
#include <cstdint>

// Problem constants (fixed shapes)
#define T_TOK 4096
#define HDIM  1024
#define FDIM  4096
#define EDIM  8
#define BM 128
#define BN 128
#define BKH 64          // K halves per slab (4 x k16 mma steps)
#define ROWB 144        // smem row stride bytes (128 data + 16 pad)
#define PADROWS 9216    // 8192 + 8*128 worst-case segment padding
#define NS1 (HDIM / BKH)       // 16
#define NS2H (FDIM / 2 / BKH)  // 32 slabs per gemm2 K-half

// ---------------- scratch (static device globals; no allocation) ----------
__device__ __align__(16) __half g_wgup[(size_t)EDIM * 2 * FDIM * HDIM];
__device__ __align__(16) __half g_wdw[(size_t)EDIM * HDIM * FDIM];
__device__ __align__(16) __half g_x16[(size_t)T_TOK * HDIM];
__device__ __align__(16) __half g_h[(size_t)PADROWS * FDIM];
__device__ __align__(16) float  g_y[(size_t)PADROWS * HDIM];
__device__ int   g_perm_token[PADROWS];
__device__ float g_perm_weight[PADROWS];
__device__ int   g_te[T_TOK * 2];
__device__ float g_tw[T_TOK * 2];
__device__ int   g_counts[EDIM];
__device__ int   g_cursor[EDIM];
__device__ int   g_off[EDIM + 1];

// ---------------- helpers ---------------------------------------------------
__device__ __forceinline__ uint32_t h2u(__half2 h) { return *(uint32_t*)&h; }

__device__ __forceinline__ uint32_t smem_u32(const void* p) {
    uint32_t a;
    asm("{ .reg .u64 t; cvta.to.shared.u64 t, %1; cvt.u32.u64 %0, t; }"
        : "=r"(a) : "l"(p));
    return a;
}

__device__ __forceinline__ void ldsm4(uint32_t& r0, uint32_t& r1,
                                      uint32_t& r2, uint32_t& r3, uint32_t addr) {
    asm volatile("ldmatrix.sync.aligned.m8n8.x4.shared.b16 {%0,%1,%2,%3}, [%4];"
                 : "=r"(r0), "=r"(r1), "=r"(r2), "=r"(r3) : "r"(addr));
}

__device__ __forceinline__ void mma_f16(float c[4], const uint32_t a[4],
                                        uint32_t b0, uint32_t b1) {
    asm volatile(
        "mma.sync.aligned.m16n8k16.row.col.f32.f16.f16.f32 "
        "{%0,%1,%2,%3}, {%4,%5,%6,%7}, {%8,%9}, {%0,%1,%2,%3};\n"
        : "+f"(c[0]), "+f"(c[1]), "+f"(c[2]), "+f"(c[3])
        : "r"(a[0]), "r"(a[1]), "r"(a[2]), "r"(a[3]), "r"(b0), "r"(b1));
}

// ---------------- fp32 -> fp16 conversion (flat) -------------------------------
__global__ void cvt_kernel(const float* __restrict__ s, __half* __restrict__ d,
                           int n8) {
    int i = blockIdx.x * blockDim.x + threadIdx.x;
    if (i >= n8) return;
    const float4* s4 = (const float4*)s + (size_t)i * 2;
    float4 v0 = s4[0], v1 = s4[1];
    uint4 o;
    o.x = h2u(__floats2half2_rn(v0.x, v0.y));
    o.y = h2u(__floats2half2_rn(v0.z, v0.w));
    o.z = h2u(__floats2half2_rn(v1.x, v1.y));
    o.w = h2u(__floats2half2_rn(v1.z, v1.w));
    ((uint4*)d)[i] = o;
}

// ---------------- cvt for one column-half of gate_up ---------------------------
__global__ void cvt_gup_half_kernel(const float* __restrict__ s,
                                    __half* __restrict__ d, int half) {
    int i = blockIdx.x * blockDim.x + threadIdx.x;
    if (i >= EDIM * 4096 * 128) return;
    int rowIdx = i >> 7;
    int chunk = i & 127;
    int e = rowIdx >> 12;
    int rr = rowIdx & 4095;
    int isUp = rr >> 11;
    int r = rr & 2047;
    size_t srcRow = (size_t)e * 8192 + (size_t)isUp * 4096 +
                    (size_t)half * 2048 + (size_t)r;
    size_t off8 = srcRow * 128 + chunk;
    const float4* s4 = (const float4*)s + off8 * 2;
    float4 v0 = s4[0], v1 = s4[1];
    uint4 o;
    o.x = h2u(__floats2half2_rn(v0.x, v0.y));
    o.y = h2u(__floats2half2_rn(v0.z, v0.w));
    o.z = h2u(__floats2half2_rn(v1.x, v1.y));
    o.w = h2u(__floats2half2_rn(v1.z, v1.w));
    ((uint4*)d)[off8] = o;
}

// ---------------- init + zero output ------------------------------------------
__global__ void init_kernel() {
    int i = blockIdx.x * blockDim.x + threadIdx.x;
    if (i < PADROWS) {
        g_perm_token[i] = -1;
        g_perm_weight[i] = 0.f;
    }
    if (i < EDIM) g_counts[i] = 0;
}

__global__ void zero_out_kernel(float* __restrict__ out) {
    int i = blockIdx.x * blockDim.x + threadIdx.x;
    if (i < T_TOK * HDIM / 4)
        ((float4*)out)[i] = make_float4(0.f, 0.f, 0.f, 0.f);
}

// ---------------- router: logits + softmax top2 -----------------------------
__global__ void __launch_bounds__(128) router_kernel(
    const float* __restrict__ x, const float* __restrict__ gw,
    float* __restrict__ logits_out) {
    __shared__ float sgw[EDIM * HDIM];
    int tid = threadIdx.x;
    for (int i = tid; i < EDIM * HDIM; i += 128) sgw[i] = gw[i];
    __syncthreads();

    int warp = tid >> 5, lane = tid & 31;
    int t = blockIdx.x * 4 + warp;
    const float* xr = x + (size_t)t * HDIM;

    float acc[EDIM];
#pragma unroll
    for (int e = 0; e < EDIM; e++) acc[e] = 0.f;
    for (int j = lane; j < HDIM; j += 32) {
        float xv = xr[j];
#pragma unroll
        for (int e = 0; e < EDIM; e++) acc[e] = fmaf(xv, sgw[e * HDIM + j], acc[e]);
    }
#pragma unroll
    for (int e = 0; e < EDIM; e++)
#pragma unroll
        for (int o = 16; o > 0; o >>= 1)
            acc[e] += __shfl_xor_sync(0xffffffffu, acc[e], o);

    if (lane == 0) {
#pragma unroll
        for (int e = 0; e < EDIM; e++) logits_out[t * EDIM + e] = acc[e];
        int e0 = 0; float l0 = acc[0];
#pragma unroll
        for (int e = 1; e < EDIM; e++) if (acc[e] > l0) { l0 = acc[e]; e0 = e; }
        int e1 = -1; float l1 = -3.4e38f;
#pragma unroll
        for (int e = 0; e < EDIM; e++)
            if (e != e0 && acc[e] > l1) { l1 = acc[e]; e1 = e; }
        float r = expf(l1 - l0);
        float w0 = 1.f / (1.f + r);
        float w1 = r / (1.f + r);
        g_te[t * 2 + 0] = e0; g_tw[t * 2 + 0] = w0;
        g_te[t * 2 + 1] = e1; g_tw[t * 2 + 1] = w1;
        atomicAdd(&g_counts[e0], 1);
        atomicAdd(&g_counts[e1], 1);
    }
}

// ---------------- scan ------------------------------------------------------
__global__ void scan_kernel() {
    int off = 0;
    for (int e = 0; e < EDIM; e++) {
        g_off[e] = off;
        g_cursor[e] = off;
        off += ((g_counts[e] + BM - 1) / BM) * BM;
    }
    g_off[EDIM] = off;
}

// ---------------- scatter ---------------------------------------------------
__global__ void scatter_kernel() {
    int t = blockIdx.x * blockDim.x + threadIdx.x;
    if (t >= T_TOK) return;
#pragma unroll
    for (int k = 0; k < 2; k++) {
        int e = g_te[t * 2 + k];
        int pos = atomicAdd(&g_cursor[e], 1);
        g_perm_token[pos] = t;
        g_perm_weight[pos] = g_tw[t * 2 + k];
    }
}

// ---------------- GEMM1: h = silu(x@w1^T) * (x@w3^T) * route_w ---------------
__global__ void __launch_bounds__(256, 1) gemm1_kernel(int n0base) {
    extern __shared__ char sm1[];
    const uint32_t ABUF = 128 * ROWB;
    const uint32_t GOFF = 128 * ROWB;
    const uint32_t BBUF = 2 * 128 * ROWB;
    char* Asm = sm1;
    char* Bsm = sm1 + 2 * ABUF;
    uint32_t asB = smem_u32(Asm);
    uint32_t bsB = smem_u32(Bsm);

    int m0 = blockIdx.x * BM;
    if (m0 >= g_off[EDIM]) return;
    int n0 = n0base + blockIdx.y * BN;
    int e = 0;
    while (m0 >= g_off[e + 1]) e++;

    int tid = threadIdx.x;
    int r = tid >> 1;
    int seg = tid & 1;

    int tok = g_perm_token[m0 + r];
    const __half* arow = (tok >= 0)
        ? g_x16 + (size_t)tok * HDIM + seg * 32 : nullptr;
    const __half* bgrow = g_wgup + ((size_t)e * 2 * FDIM + (n0 + r)) * HDIM + seg * 32;
    const __half* burow = bgrow + (size_t)FDIM * HDIM;
    uint32_t stoff = (uint32_t)(r * ROWB + seg * 64);

    int warp = tid >> 5, lane = tid & 31;
    int gid = lane >> 2, tig = lane & 3;
    int wm = (warp & 1) * 64;
    int wn = (warp >> 1) * 32;

    uint32_t aLrow = (uint32_t)(wm + (lane & 15));
    uint32_t aLcol = (uint32_t)((lane >> 4) * 16);
    uint32_t bLrow = (uint32_t)(wn + (lane & 7) + ((lane >> 4) & 1) * 8);
    uint32_t bLcol = (uint32_t)(((lane >> 3) & 1) * 16);

    float acc[2][4][4][4];
#pragma unroll
    for (int g = 0; g < 2; g++)
#pragma unroll
        for (int mt = 0; mt < 4; mt++)
#pragma unroll
            for (int nt = 0; nt < 4; nt++)
#pragma unroll
                for (int i = 0; i < 4; i++) acc[g][mt][nt][i] = 0.f;

    const uint4 z4 = make_uint4(0, 0, 0, 0);
    uint4 pA[4], pG[4], pU[4];
#pragma unroll
    for (int i = 0; i < 4; i++) {
        pA[i] = arow ? *(const uint4*)(arow + i * 8) : z4;
        pG[i] = *(const uint4*)(bgrow + i * 8);
        pU[i] = *(const uint4*)(burow + i * 8);
    }

    for (int s = 0; s < NS1; s++) {
        int buf = s & 1;
        char* At = Asm + buf * ABUF;
        char* Bt = Bsm + buf * BBUF;
#pragma unroll
        for (int i = 0; i < 4; i++) {
            *(uint4*)(At + stoff + i * 16) = pA[i];
            *(uint4*)(Bt + stoff + i * 16) = pG[i];
            *(uint4*)(Bt + GOFF + stoff + i * 16) = pU[i];
        }
        __syncthreads();

        if (s + 1 < NS1) {
            int k = (s + 1) * BKH;
#pragma unroll
            for (int i = 0; i < 4; i++) {
                pA[i] = arow ? *(const uint4*)(arow + k + i * 8) : z4;
                pG[i] = *(const uint4*)(bgrow + k + i * 8);
                pU[i] = *(const uint4*)(burow + k + i * 8);
            }
        }

        uint32_t aTile = asB + buf * ABUF;
        uint32_t bTile = bsB + buf * BBUF;
#pragma unroll
        for (int ks = 0; ks < 4; ks++) {
            uint32_t kbA = ks * 32 + aLcol;
            uint32_t kbB = ks * 32 + bLcol;
            uint32_t a[4][4];
#pragma unroll
            for (int mt = 0; mt < 4; mt++)
                ldsm4(a[mt][0], a[mt][1], a[mt][2], a[mt][3],
                      aTile + (aLrow + mt * 16) * ROWB + kbA);
#pragma unroll
            for (int g = 0; g < 2; g++) {
#pragma unroll
                for (int np = 0; np < 2; np++) {
                    uint32_t b0, b1, b2, b3;
                    ldsm4(b0, b1, b2, b3,
                          bTile + g * GOFF + (bLrow + np * 16) * ROWB + kbB);
#pragma unroll
                    for (int mt = 0; mt < 4; mt++) {
                        mma_f16(acc[g][mt][np * 2 + 0], a[mt], b0, b1);
                        mma_f16(acc[g][mt][np * 2 + 1], a[mt], b2, b3);
                    }
                }
            }
        }
    }

#pragma unroll
    for (int mt = 0; mt < 4; mt++) {
        int rbase = m0 + wm + mt * 16 + gid;
        float wA = g_perm_weight[rbase];
        float wB = g_perm_weight[rbase + 8];
#pragma unroll
        for (int nt = 0; nt < 4; nt++) {
            int cbase = n0 + wn + nt * 8 + 2 * tig;
            float h0 = (acc[0][mt][nt][0] / (1.f + expf(-acc[0][mt][nt][0]))) *
                       acc[1][mt][nt][0] * wA;
            float h1 = (acc[0][mt][nt][1] / (1.f + expf(-acc[0][mt][nt][1]))) *
                       acc[1][mt][nt][1] * wA;
            float h2 = (acc[0][mt][nt][2] / (1.f + expf(-acc[0][mt][nt][2]))) *
                       acc[1][mt][nt][2] * wB;
            float h3 = (acc[0][mt][nt][3] / (1.f + expf(-acc[0][mt][nt][3]))) *
                       acc[1][mt][nt][3] * wB;
            *(uint32_t*)&g_h[(size_t)rbase * FDIM + cbase] =
                h2u(__floats2half2_rn(h0, h1));
            *(uint32_t*)&g_h[(size_t)(rbase + 8) * FDIM + cbase] =
                h2u(__floats2half2_rn(h2, h3));
        }
    }
}

// ---------------- GEMM2 (K-split): stageB=0 writes g_y partial over K half 0;
//                  stageB=1 computes K half 1, adds g_y, atomicAdds into out. ---
__global__ void __launch_bounds__(256, 1) gemm2_kernel(float* __restrict__ out,
                                                       int kbase, int stageB) {
    extern __shared__ char sm2[];
    const uint32_t ABUF = 128 * ROWB;
    const uint32_t BBUF = 128 * ROWB;
    char* Asm = sm2;
    char* Bsm = sm2 + 2 * ABUF;
    uint32_t asB = smem_u32(Asm);
    uint32_t bsB = smem_u32(Bsm);

    int m0 = blockIdx.x * BM;
    if (m0 >= g_off[EDIM]) return;
    int n0 = blockIdx.y * BN;
    int e = 0;
    while (m0 >= g_off[e + 1]) e++;

    int tid = threadIdx.x;
    int r = tid >> 1;
    int seg = tid & 1;

    const __half* arow = g_h + (size_t)(m0 + r) * FDIM + kbase + seg * 32;
    const __half* brow = g_wdw + ((size_t)e * HDIM + (n0 + r)) * FDIM + kbase + seg * 32;
    uint32_t stoff = (uint32_t)(r * ROWB + seg * 64);

    int warp = tid >> 5, lane = tid & 31;
    int gid = lane >> 2, tig = lane & 3;
    int wm = (warp & 1) * 64;
    int wn = (warp >> 1) * 32;

    uint32_t aLrow = (uint32_t)(wm + (lane & 15));
    uint32_t aLcol = (uint32_t)((lane >> 4) * 16);
    uint32_t bLrow = (uint32_t)(wn + (lane & 7) + ((lane >> 4) & 1) * 8);
    uint32_t bLcol = (uint32_t)(((lane >> 3) & 1) * 16);

    float acc[4][4][4];
#pragma unroll
    for (int mt = 0; mt < 4; mt++)
#pragma unroll
        for (int nt = 0; nt < 4; nt++)
#pragma unroll
            for (int i = 0; i < 4; i++) acc[mt][nt][i] = 0.f;

    uint4 pA[4], pB[4];
#pragma unroll
    for (int i = 0; i < 4; i++) {
        pA[i] = *(const uint4*)(arow + i * 8);
        pB[i] = *(const uint4*)(brow + i * 8);
    }

    for (int s = 0; s < NS2H; s++) {
        int buf = s & 1;
        char* At = Asm + buf * ABUF;
        char* Bt = Bsm + buf * BBUF;
#pragma unroll
        for (int i = 0; i < 4; i++) {
            *(uint4*)(At + stoff + i * 16) = pA[i];
            *(uint4*)(Bt + stoff + i * 16) = pB[i];
        }
        __syncthreads();

        if (s + 1 < NS2H) {
            int k = (s + 1) * BKH;
#pragma unroll
            for (int i = 0; i < 4; i++) {
                pA[i] = *(const uint4*)(arow + k + i * 8);
                pB[i] = *(const uint4*)(brow + k + i * 8);
            }
        }

        uint32_t aTile = asB + buf * ABUF;
        uint32_t bTile = bsB + buf * BBUF;
#pragma unroll
        for (int ks = 0; ks < 4; ks++) {
            uint32_t kbA = ks * 32 + aLcol;
            uint32_t kbB = ks * 32 + bLcol;
            uint32_t a[4][4];
#pragma unroll
            for (int mt = 0; mt < 4; mt++)
                ldsm4(a[mt][0], a[mt][1], a[mt][2], a[mt][3],
                      aTile + (aLrow + mt * 16) * ROWB + kbA);
#pragma unroll
            for (int np = 0; np < 2; np++) {
                uint32_t b0, b1, b2, b3;
                ldsm4(b0, b1, b2, b3,
                      bTile + (bLrow + np * 16) * ROWB + kbB);
#pragma unroll
                for (int mt = 0; mt < 4; mt++) {
                    mma_f16(acc[mt][np * 2 + 0], a[mt], b0, b1);
                    mma_f16(acc[mt][np * 2 + 1], a[mt], b2, b3);
                }
            }
        }
    }

    if (!stageB) {
        // stage A: write fp32 partials to g_y (row-unique -> deterministic)
#pragma unroll
        for (int mt = 0; mt < 4; mt++) {
            int rbase = m0 + wm + mt * 16 + gid;
#pragma unroll
            for (int nt = 0; nt < 4; nt++) {
                int cbase = n0 + wn + nt * 8 + 2 * tig;
                *(float2*)&g_y[(size_t)rbase * HDIM + cbase] =
                    make_float2(acc[mt][nt][0], acc[mt][nt][1]);
                *(float2*)&g_y[(size_t)(rbase + 8) * HDIM + cbase] =
                    make_float2(acc[mt][nt][2], acc[mt][nt][3]);
            }
        }
    } else {
        // stage B: total = partial + acc; atomicAdd into out (2 contributors
        // per element -> commutative -> deterministic)
#pragma unroll
        for (int mt = 0; mt < 4; mt++) {
            int rbase = m0 + wm + mt * 16 + gid;
            int tok0 = g_perm_token[rbase];
            int tok1 = g_perm_token[rbase + 8];
#pragma unroll
            for (int nt = 0; nt < 4; nt++) {
                int cbase = n0 + wn + nt * 8 + 2 * tig;
                float2 y0 = *(float2*)&g_y[(size_t)rbase * HDIM + cbase];
                float2 y1 = *(float2*)&g_y[(size_t)(rbase + 8) * HDIM + cbase];
                if (tok0 >= 0) {
                    atomicAdd(&out[(size_t)tok0 * HDIM + cbase],
                              acc[mt][nt][0] + y0.x);
                    atomicAdd(&out[(size_t)tok0 * HDIM + cbase + 1],
                              acc[mt][nt][1] + y0.y);
                }
                if (tok1 >= 0) {
                    atomicAdd(&out[(size_t)tok1 * HDIM + cbase],
                              acc[mt][nt][2] + y1.x);
                    atomicAdd(&out[(size_t)tok1 * HDIM + cbase + 1],
                              acc[mt][nt][3] + y1.y);
                }
            }
        }
    }
}

// ---------------- launcher ----------------------------------------------------
extern "C" void kernel_launch(void* const* d_in, const int* in_sizes, int n_in,
                              void* d_out, int out_size) {
    const float* x   = (const float*)d_in[0];   // (2,2048,1024)
    const float* gw  = (const float*)d_in[1];   // (8,1024)
    const float* gup = (const float*)d_in[2];   // (8,8192,1024)
    const float* dw  = (const float*)d_in[3];   // (8,1024,4096)
    float* out = (float*)d_out;                 // out (4194304) ++ logits (32768)
    float* logits = out + (size_t)T_TOK * HDIM;

    const int smem1 = 2 * 128 * ROWB + 2 * 2 * 128 * ROWB;  // 110592 B
    const int smem2 = 2 * 128 * ROWB + 2 * 128 * ROWB;      //  73728 B
    cudaFuncSetAttribute(gemm1_kernel, cudaFuncAttributeMaxDynamicSharedMemorySize, smem1);
    cudaFuncSetAttribute(gemm2_kernel, cudaFuncAttributeMaxDynamicSharedMemorySize, smem2);

    __half* d_wgup; cudaGetSymbolAddress((void**)&d_wgup, g_wgup);
    __half* d_wdw;  cudaGetSymbolAddress((void**)&d_wdw,  g_wdw);
    __half* d_x16;  cudaGetSymbolAddress((void**)&d_x16,  g_x16);

    static cudaStream_t s2 = nullptr, s3 = nullptr, s4 = nullptr;
    static cudaEvent_t evFork = nullptr, evCvt0 = nullptr, evH1 = nullptr,
                       evDW = nullptr, evRoute = nullptr, evG1h0 = nullptr,
                       evA = nullptr;
    if (!s2) {
        cudaStreamCreateWithFlags(&s2, cudaStreamNonBlocking);
        cudaStreamCreateWithFlags(&s3, cudaStreamNonBlocking);
        cudaStreamCreateWithFlags(&s4, cudaStreamNonBlocking);
        cudaEventCreateWithFlags(&evFork, cudaEventDisableTiming);
        cudaEventCreateWithFlags(&evCvt0, cudaEventDisableTiming);
        cudaEventCreateWithFlags(&evH1, cudaEventDisableTiming);
        cudaEventCreateWithFlags(&evDW, cudaEventDisableTiming);
        cudaEventCreateWithFlags(&evRoute, cudaEventDisableTiming);
        cudaEventCreateWithFlags(&evG1h0, cudaEventDisableTiming);
        cudaEventCreateWithFlags(&evA, cudaEventDisableTiming);
    }

    cudaEventRecord(evFork, 0);
    cudaStreamWaitEvent(s3, evFork, 0);

    // s3: output zero + routing chain (hidden under cvts on main)
    zero_out_kernel<<<(T_TOK * HDIM / 4 + 255) / 256, 256, 0, s3>>>(out);
    init_kernel<<<(PADROWS + 255) / 256, 256, 0, s3>>>();
    router_kernel<<<T_TOK / 4, 128, 0, s3>>>(x, gw, logits);
    scan_kernel<<<1, 1, 0, s3>>>();
    scatter_kernel<<<(T_TOK + 255) / 256, 256, 0, s3>>>();
    cudaEventRecord(evRoute, s3);

    // main: x cvt + first gate_up half (minimal serial prefix)
    cvt_kernel<<<(T_TOK * HDIM / 8 + 255) / 256, 256>>>(x, d_x16,
        T_TOK * HDIM / 8);
    cvt_gup_half_kernel<<<(EDIM * 4096 * 128 + 255) / 256, 256>>>(gup, d_wgup, 0);
    cudaEventRecord(evCvt0, 0);

    // s2: second gate_up half + down weights (overlap gemm1 half 0)
    cudaStreamWaitEvent(s2, evCvt0, 0);
    cvt_gup_half_kernel<<<(EDIM * 4096 * 128 + 255) / 256, 256, 0, s2>>>(
        gup, d_wgup, 1);
    cudaEventRecord(evH1, s2);
    cvt_kernel<<<(EDIM * HDIM * FDIM / 8 + 255) / 256, 256, 0, s2>>>(
        dw, d_wdw, EDIM * HDIM * FDIM / 8);
    cudaEventRecord(evDW, s2);

    // main: gemm1 half 0 (produces g_h cols [0,2048))
    cudaStreamWaitEvent(0, evRoute, 0);
    gemm1_kernel<<<dim3(PADROWS / BM, 16), 256, smem1>>>(0);
    cudaEventRecord(evG1h0, 0);

    // s4: gemm2 stage A (K half 0) — overlaps gemm1 half 1, fills its tail
    cudaStreamWaitEvent(s4, evG1h0, 0);
    cudaStreamWaitEvent(s4, evDW, 0);
    gemm2_kernel<<<dim3(PADROWS / BM, HDIM / BN), 256, smem2, s4>>>(out, 0, 0);
    cudaEventRecord(evA, s4);

    // main: gemm1 half 1, then gemm2 stage B (needs g_h cols [2048,4096) + g_y)
    cudaStreamWaitEvent(0, evH1, 0);
    gemm1_kernel<<<dim3(PADROWS / BM, 16), 256, smem1>>>(2048);
    cudaStreamWaitEvent(0, evA, 0);
    gemm2_kernel<<<dim3(PADROWS / BM, HDIM / BN), 256, smem2>>>(out, FDIM / 2, 1);
    (void)in_sizes; (void)n_in; (void)out_size;
}